// round 16
// baseline (speedup 1.0000x reference)
#include <cuda_runtime.h>
#include <math_constants.h>

#define NP 512
#define NR 256
#define NS 256
#define CHUNK 32
#define NCH (NR / CHUNK)
#define SMS 260              // padded float stride (260 = 65 float4) -> conflict-free

// value-desc, index-asc ordering (matches jax.lax.top_k)
__device__ __forceinline__ bool gt(float v, int i, float w, int j) {
    return (v > w) || ((v == w) && (i < j));
}
// Tie-aware insert into descending triple
__device__ __forceinline__ void insT(float v, int idx,
                                     float &a, float &b, float &c,
                                     int &ai, int &bi, int &ci) {
    if (gt(v, idx, c, ci)) {
        if (gt(v, idx, b, bi)) {
            c = b; ci = bi;
            if (gt(v, idx, a, ai)) { b = a; bi = ai; a = v; ai = idx; }
            else                   { b = v; bi = idx; }
        } else { c = v; ci = idx; }
    }
}
// Strict-> insert: exact when indices arrive in ascending order.
__device__ __forceinline__ void insS(float v, int idx,
                                     float &a, float &b, float &c,
                                     int &ai, int &bi, int &ci) {
    if (v > c) {
        if (v > b) {
            c = b; ci = bi;
            if (v > a) { b = a; bi = ai; a = v; ai = idx; }
            else       { b = v; bi = idx; }
        } else { c = v; ci = idx; }
    }
}

__global__ __launch_bounds__(256) void iapm_fused(
    const float* __restrict__ score,
    const int*   __restrict__ ref_mask,
    const int*   __restrict__ src_mask,
    float* __restrict__ out_score,
    float* __restrict__ out_corr)
{
    __shared__ float  tile[CHUNK * SMS];     // 33.3 KB staging tile
    __shared__ float4 rowv[NR];              // (0.5e^v0, 0.5e^v1, 0.5e^v2, idxpack|rm<<24)
    __shared__ unsigned char smr[NR];

    const int tid  = threadIdx.x;
    const int lane = tid & 31;
    const int w    = tid >> 5;
    const int grp  = lane >> 3;              // 8-lane group -> 4 rows per warp
    const int x    = lane & 7;
    const int p    = blockIdx.x;
    const float* base = score + (size_t)p * NR * NS;

    smr[tid] = (ref_mask[p * NR + tid] != 0) ? 1 : 0;
    const bool ms = src_mask[p * NS + tid] != 0;
    __syncthreads();                         // smr visible to publishers

    // Column top-3 state lives in registers across all chunks (thread = column tid)
    float ca = -CUDART_INF_F, cb = -CUDART_INF_F, cc = -CUDART_INF_F;
    int   cai = 0x7fffffff, cbi = 0x7fffffff, cci = 0x7fffffff;

    for (int ch = 0; ch < NCH; ++ch) {
        const int r0 = ch * CHUNK;
        const int rr = w * 4 + grp;          // local row this thread scans

        // Load this thread's 8 float4s of row rr straight to registers (coalesced:
        // each quarter-warp covers 128B contiguous).
        float4 f[8];
        const float4* g4 = (const float4*)(base + (size_t)(r0 + rr) * NS);
        #pragma unroll
        for (int j = 0; j < 8; ++j) f[j] = g4[x + 8 * j];

        // Row scan from registers (ascending idx per lane) + stage to smem.
        float a = -CUDART_INF_F, b = -CUDART_INF_F, c = -CUDART_INF_F;
        int ai = 0x7fffffff, bi = 0x7fffffff, ci = 0x7fffffff;
        #pragma unroll
        for (int j = 0; j < 8; ++j) {
            *(float4*)&tile[rr * SMS + 4 * (x + 8 * j)] = f[j];
            const int ib = 4 * (x + 8 * j);
            insS(f[j].x, ib + 0, a, b, c, ai, bi, ci);
            insS(f[j].y, ib + 1, a, b, c, ai, bi, ci);
            insS(f[j].z, ib + 2, a, b, c, ai, bi, ci);
            insS(f[j].w, ib + 3, a, b, c, ai, bi, ci);
        }
        // Merge across the 8-lane group (explicit tie-break across lanes).
        #pragma unroll
        for (int off = 4; off; off >>= 1) {
            float oa = __shfl_down_sync(0xFFFFFFFFu, a, off, 8);
            float ob = __shfl_down_sync(0xFFFFFFFFu, b, off, 8);
            float oc_ = __shfl_down_sync(0xFFFFFFFFu, c, off, 8);
            int  oai = __shfl_down_sync(0xFFFFFFFFu, ai, off, 8);
            int  obi = __shfl_down_sync(0xFFFFFFFFu, bi, off, 8);
            int  oci = __shfl_down_sync(0xFFFFFFFFu, ci, off, 8);
            insT(oa, oai, a, b, c, ai, bi, ci);
            insT(ob, obi, a, b, c, ai, bi, ci);
            insT(oc_, oci, a, b, c, ai, bi, ci);
        }
        if (x == 0) {
            unsigned pack = (unsigned)ai | ((unsigned)bi << 8) | ((unsigned)ci << 16)
                          | ((unsigned)smr[r0 + rr] << 24);
            rowv[r0 + rr] = make_float4(0.5f * expf(a), 0.5f * expf(b),
                                        0.5f * expf(c), __uint_as_float(pack));
        }
        __syncthreads();                     // tile fully staged

        // Column pass: thread = column tid, ascending global r (tie-exact).
        #pragma unroll
        for (int r = 0; r < CHUNK; ++r)
            insS(tile[r * SMS + tid], r0 + r, ca, cb, cc, cai, cbi, cci);
        __syncthreads();                     // done before next chunk overwrites tile
    }

    // ---- Fill phase: fully coalesced, all state in smem/regs ----
    const float w0 = 0.5f * expf(ca), w1 = 0.5f * expf(cb), w2 = 0.5f * expf(cc);
    const int   c0 = cai, c1 = cbi, c2 = cci;
    float* os = out_score + (size_t)p * NR * NS + tid;
    float* oc = out_corr  + (size_t)p * NR * NS + tid;

    #pragma unroll 4
    for (int r = 0; r < NR; ++r) {
        float4 rv = rowv[r];                 // broadcast LDS.128
        unsigned pk = __float_as_uint(rv.w);
        int i0 = pk & 255, i1 = (pk >> 8) & 255, i2 = (pk >> 16) & 255;
        bool rm = (pk >> 24) != 0;
        float v = (tid == i0) ? rv.x : (tid == i1) ? rv.y : (tid == i2) ? rv.z : 0.0f;
        float wv = (r == c0) ? w0 : (r == c1) ? w1 : (r == c2) ? w2 : 0.0f;
        float sc = v + wv;                   // halves pre-scaled by 0.5
        os[r * NS] = sc;
        oc[r * NS] = (rm && ms && (sc > 0.0f)) ? 1.0f : 0.0f;
    }
}

extern "C" void kernel_launch(void* const* d_in, const int* in_sizes, int n_in,
                              void* d_out, int out_size) {
    // inputs: matching_score_map [P,R,S] f32, node_corr_scores [P] f32 (unused),
    //         ref_knn_masks [P,R] bool(4B words), src_knn_masks [P,S] bool(4B words)
    const float* score = (const float*)d_in[0];
    const int*   refm  = (const int*)d_in[2];
    const int*   srcm  = (const int*)d_in[3];

    float* out = (float*)d_out;
    size_t total = (size_t)NP * NR * NS;
    float* out_corr = out + total;           // [score_map f32 | corr_map bool->f32]

    iapm_fused<<<NP, 256>>>(score, refm, srcm, out, out_corr);
}